// round 8
// baseline (speedup 1.0000x reference)
#include <cuda_runtime.h>
#include <cuda_fp16.h>

// Problem constants (fixed by the dataset):
//   x:     (B, 3)  float32, B = 131072
//   knots: (3, 48) float32   (uniform linspace per dim)
//   grid:  (48, 48, 48, 16) float32
//   out:   (B, 16) float32
#define NK 48
#define NP 50          // padded extent (NK + 2)
#define NV 16
#define TS 8           // cells per tile per dim
#define NT 6           // tiles per dim (ceil(47/8))
#define TILES (NT * NT * NT)          // 216
#define SL 11          // slab extent per dim (TS + 3)
#define MAXB 131072

// Scratch (__device__ globals; no allocation).
__device__ __align__(256) __half g_pad[NP * NP * NP * NV];  // 4 MB padded fp16 grid
__device__ int g_count[TILES];
__device__ int g_off[TILES + 1];
__device__ int g_cursor[TILES];
__device__ int g_tidx[MAXB];
__device__ int g_sorted[MAXB];

// Shared closed-form cell index (uniform knots): MUST be identical in bin+interp.
__device__ __forceinline__ int cell_index(float xd, float k0, float kN, float* u_out) {
    float t = (xd - k0) * __fdividef((float)(NK - 1), kN - k0);
    int idx = __float2int_rd(t);
    idx = idx < 0 ? 0 : (idx > NK - 2 ? NK - 2 : idx);
    if (u_out) *u_out = t - (float)idx;
    return idx;
}

// ---------------------------------------------------------------------------
// Padded grid (linear extrapolation), single fp16 copy. 2 threads per cell.
// ---------------------------------------------------------------------------
__device__ __forceinline__ int pad_terms(int I, int* s, float* c) {
    if (I == 0)      { s[0] = 0;      c[0] = 2.0f; s[1] = 1;      c[1] = -1.0f; return 2; }
    if (I == NP - 1) { s[0] = NK - 1; c[0] = 2.0f; s[1] = NK - 2; c[1] = -1.0f; return 2; }
    s[0] = I - 1; c[0] = 1.0f; return 1;
}

__global__ void pad_kernel(const float* __restrict__ grid) {
    int tid = blockIdx.x * blockDim.x + threadIdx.x;
    const int TOT = NP * NP * NP;
    int idx  = tid >> 1;
    int half = tid & 1;
    if (idx >= TOT) return;
    int K = idx % NP;
    int t = idx / NP;
    int J = t % NP;
    int I = t / NP;

    int si[2], sj[2], skk[2];
    float ci[2], cj[2], ck[2];
    int ni = pad_terms(I, si, ci);
    int nj = pad_terms(J, sj, cj);
    int nk = pad_terms(K, skk, ck);

    float v[8];
    #pragma unroll
    for (int q = 0; q < 8; q++) v[q] = 0.0f;

    for (int a = 0; a < ni; a++)
        for (int b = 0; b < nj; b++)
            for (int c = 0; c < nk; c++) {
                float w = ci[a] * cj[b] * ck[c];
                const float* src = grid + ((si[a] * NK + sj[b]) * NK + skk[c]) * NV + half * 8;
                #pragma unroll
                for (int q = 0; q < 8; q++) v[q] += w * src[q];
            }

    __half2 h[4];
    #pragma unroll
    for (int q = 0; q < 4; q++)
        h[q] = __halves2half2(__float2half_rn(v[2 * q]), __float2half_rn(v[2 * q + 1]));
    *reinterpret_cast<uint4*>(g_pad + idx * NV + half * 8) = *reinterpret_cast<const uint4*>(h);
}

// ---------------------------------------------------------------------------
// Binning: zero -> per-block smem histogram -> scan -> block-aggregated scatter
// ---------------------------------------------------------------------------
__global__ void zero_kernel() {
    int t = threadIdx.x;
    if (t < TILES) g_count[t] = 0;
}

__global__ __launch_bounds__(1024) void bin_kernel(const float* __restrict__ x,
                                                   const float* __restrict__ knots, int B) {
    __shared__ int h[TILES];
    int tid = threadIdx.x;
    if (tid < TILES) h[tid] = 0;
    __syncthreads();
    int pid = blockIdx.x * 1024 + tid;
    int t = 0;
    bool ok = pid < B;
    if (ok) {
        int b0 = cell_index(__ldg(x + pid * 3 + 0), __ldg(knots),            __ldg(knots + NK - 1), 0);
        int b1 = cell_index(__ldg(x + pid * 3 + 1), __ldg(knots + NK),       __ldg(knots + 2 * NK - 1), 0);
        int b2 = cell_index(__ldg(x + pid * 3 + 2), __ldg(knots + 2 * NK),   __ldg(knots + 3 * NK - 1), 0);
        t = (b0 >> 3) * (NT * NT) + (b1 >> 3) * NT + (b2 >> 3);
        g_tidx[pid] = t;
        atomicAdd(&h[t], 1);
    }
    __syncthreads();
    if (tid < TILES && h[tid]) atomicAdd(&g_count[tid], h[tid]);
}

__global__ void scan_kernel() {
    __shared__ int s[256];
    int t = threadIdx.x;
    int v = (t < TILES) ? g_count[t] : 0;
    s[t] = v;
    __syncthreads();
    #pragma unroll
    for (int d = 1; d < 256; d <<= 1) {
        int u = (t >= d) ? s[t - d] : 0;
        __syncthreads();
        s[t] += u;
        __syncthreads();
    }
    if (t < TILES) {
        g_off[t + 1]  = s[t];
        g_cursor[t]   = s[t] - v;   // exclusive prefix
    }
    if (t == 0) g_off[0] = 0;
}

__global__ __launch_bounds__(1024) void scatter_kernel(int B) {
    __shared__ int h[TILES];
    __shared__ int base[TILES];
    int tid = threadIdx.x;
    if (tid < TILES) h[tid] = 0;
    __syncthreads();
    int pid = blockIdx.x * 1024 + tid;
    int t = 0, lr = 0;
    bool ok = pid < B;
    if (ok) {
        t = g_tidx[pid];
        lr = atomicAdd(&h[t], 1);
    }
    __syncthreads();
    if (tid < TILES && h[tid]) base[tid] = atomicAdd(&g_cursor[tid], h[tid]);
    __syncthreads();
    if (ok) g_sorted[base[t] + lr] = pid;
}

// ---------------------------------------------------------------------------
// Interp: 2 CTAs per tile. CTA loads the tile's 11^3 fp16 slab into smem,
// then processes its half of the tile's points: 8 lanes/point
// (k = l>>1, channel half = l&1), j-contraction fp16, i + k in f32x2.
// ---------------------------------------------------------------------------
__device__ __forceinline__ unsigned long long pack_f32x2(float lo, float hi) {
    unsigned long long r;
    asm("mov.b64 %0, {%1, %2};" : "=l"(r) : "f"(lo), "f"(hi));
    return r;
}

__global__ __launch_bounds__(256)
void interp_kernel(const float* __restrict__ x,
                   const float* __restrict__ knots,
                   float4* __restrict__ out) {
    __shared__ __half slab[SL * SL * SL * NV];   // 42592 B

    const int bx   = blockIdx.x;
    const int tile = bx >> 1;
    const int hcta = bx & 1;
    const int ti = tile / (NT * NT);
    const int tj = (tile / NT) % NT;
    const int tk = tile % NT;
    const int gi0 = ti * TS, gj0 = tj * TS, gk0 = tk * TS;

    // ---- slab load: 121 (i,j) rows x 22 uint4 (11 k-cells x 16 ch) ----
    for (int idx = threadIdx.x; idx < 121 * 22; idx += 256) {
        int row = idx / 22, q = idx % 22;
        int li = row / SL, lj = row % SL;
        int si = min(gi0 + li, NP - 1);
        int sj = min(gj0 + lj, NP - 1);
        int sk = min(gk0 + (q >> 1), NP - 1);
        uint4 v = *reinterpret_cast<const uint4*>(
            g_pad + ((si * NP + sj) * NP + sk) * NV + (q & 1) * 8);
        *reinterpret_cast<uint4*>(
            &slab[((li * SL + lj) * SL + (q >> 1)) * NV + (q & 1) * 8]) = v;
    }
    __syncthreads();

    const int s0  = g_off[tile];
    const int cnt = g_off[tile + 1] - s0;
    const int c0  = (cnt + 1) >> 1;
    const int start = hcta ? s0 + c0 : s0;
    const int end   = hcta ? s0 + cnt : s0 + c0;

    const int l = threadIdx.x & 7;
    const unsigned grp_mask = 0xFFu << (threadIdx.x & 24);

    const float k0x = __ldg(knots),           kNx = __ldg(knots + NK - 1);
    const float k0y = __ldg(knots + NK),      kNy = __ldg(knots + 2 * NK - 1);
    const float k0z = __ldg(knots + 2 * NK),  kNz = __ldg(knots + 3 * NK - 1);

    const int strideI = SL * SL * NV;   // 1936 halves
    const int strideJ = SL * NV;        // 176 halves

    for (int it = start + (threadIdx.x >> 3); it < end; it += 32) {
        const int pid = __ldg(g_sorted + it);

        // per-lane weights for all 3 dims (no broadcast shuffles)
        float u0, u1, u2s;
        const int b0 = cell_index(__ldg(x + pid * 3 + 0), k0x, kNx, &u0);
        const int b1 = cell_index(__ldg(x + pid * 3 + 1), k0y, kNy, &u1);
        const int b2 = cell_index(__ldg(x + pid * 3 + 2), k0z, kNz, &u2s);

        float w0[4], w1f[4], w2[4];
        {
            float us[3] = {u0, u1, u2s};
            float* wall[3] = {w0, w1f, w2};
            #pragma unroll
            for (int d = 0; d < 3; d++) {
                float u  = us[d];
                float uu = u * u;
                float u3 = uu * u;
                wall[d][0] = -0.5f * u3 +        uu - 0.5f * u;
                wall[d][1] =  1.5f * u3 - 2.5f * uu + 1.0f;
                wall[d][2] = -1.5f * u3 + 2.0f * uu + 0.5f * u;
                wall[d][3] =  0.5f * u3 - 0.5f * uu;
            }
        }

        const int kk = l >> 1;
        const float wk = (kk == 0) ? w2[0] : (kk == 1) ? w2[1] : (kk == 2) ? w2[2] : w2[3];

        __half2 w1h[4];
        #pragma unroll
        for (int j = 0; j < 4; j++) w1h[j] = __float2half2_rn(w1f[j]);

        // lane's smem base: cell (b0-gi0, b1-gj0, b2-gk0+kk), channel half l&1
        const __half* sb = slab
            + (((b0 - gi0) * SL + (b1 - gj0)) * SL + (b2 - gk0) + kk) * NV
            + (l & 1) * 8;

        unsigned long long acc2[4];
        #pragma unroll
        for (int i = 0; i < 4; i++) {
            uint4 r0 = *reinterpret_cast<const uint4*>(sb + i * strideI);
            uint4 r1 = *reinterpret_cast<const uint4*>(sb + i * strideI + strideJ);
            uint4 r2 = *reinterpret_cast<const uint4*>(sb + i * strideI + 2 * strideJ);
            uint4 r3 = *reinterpret_cast<const uint4*>(sb + i * strideI + 3 * strideJ);

            const __half2* h0 = reinterpret_cast<const __half2*>(&r0);
            const __half2* h1 = reinterpret_cast<const __half2*>(&r1);
            const __half2* h2 = reinterpret_cast<const __half2*>(&r2);
            const __half2* h3 = reinterpret_cast<const __half2*>(&r3);

            const float wi = w0[i] * wk;
            const unsigned long long wi2 = pack_f32x2(wi, wi);

            #pragma unroll
            for (int q = 0; q < 4; q++) {
                __half2 hacc = __hmul2(w1h[0], h0[q]);
                hacc = __hfma2(w1h[1], h1[q], hacc);
                hacc = __hfma2(w1h[2], h2[q], hacc);
                hacc = __hfma2(w1h[3], h3[q], hacc);
                float2 f = __half22float2(hacc);
                unsigned long long fv = pack_f32x2(f.x, f.y);
                if (i == 0) {
                    asm("mul.rn.f32x2 %0, %1, %2;" : "=l"(acc2[q]) : "l"(fv), "l"(wi2));
                } else {
                    asm("fma.rn.f32x2 %0, %1, %2, %0;" : "+l"(acc2[q]) : "l"(fv), "l"(wi2));
                }
            }
        }

        // reduce over k within the 8-lane group (lanes sharing l&1)
        #pragma unroll
        for (int q = 0; q < 4; q++) {
            unsigned long long o = __shfl_xor_sync(grp_mask, acc2[q], 2);
            asm("add.rn.f32x2 %0, %0, %1;" : "+l"(acc2[q]) : "l"(o));
        }
        #pragma unroll
        for (int q = 0; q < 4; q++) {
            unsigned long long o = __shfl_xor_sync(grp_mask, acc2[q], 4);
            asm("add.rn.f32x2 %0, %0, %1;" : "+l"(acc2[q]) : "l"(o));
        }

        if (l < 2) {
            float rr[8];
            #pragma unroll
            for (int q = 0; q < 4; q++)
                asm("mov.b64 {%0, %1}, %2;" : "=f"(rr[2 * q]), "=f"(rr[2 * q + 1]) : "l"(acc2[q]));
            out[pid * 4 + l * 2]     = make_float4(rr[0], rr[1], rr[2], rr[3]);
            out[pid * 4 + l * 2 + 1] = make_float4(rr[4], rr[5], rr[6], rr[7]);
        }
    }
}

extern "C" void kernel_launch(void* const* d_in, const int* in_sizes, int n_in,
                              void* d_out, int out_size) {
    const float* x     = (const float*)d_in[0];   // (B, 3)
    const float* knots = (const float*)d_in[1];   // (3, 48)
    const float* grid  = (const float*)d_in[2];   // (48, 48, 48, 16)
    float4* out = (float4*)d_out;                 // (B, 16)

    int B = in_sizes[0] / 3;

    // padded fp16 grid (independent of binning)
    const int TOT = NP * NP * NP;
    pad_kernel<<<(TOT * 2 + 255) / 256, 256>>>(grid);

    // binning pipeline
    zero_kernel<<<1, 256>>>();
    bin_kernel<<<(B + 1023) / 1024, 1024>>>(x, knots, B);
    scan_kernel<<<1, 256>>>();
    scatter_kernel<<<(B + 1023) / 1024, 1024>>>(B);

    // tiled interpolation: 2 CTAs per tile
    interp_kernel<<<TILES * 2, 256>>>(x, knots, out);
}